// round 16
// baseline (speedup 1.0000x reference)
#include <cuda_runtime.h>
#include <cstdint>

// CrossCCC via tf32 mma.sync.m16n8k8 + cp.async double-buffered tiles.
// NO per-thread accumulator arrays (they spilled): diagonal lags are
// carry-chained across adjacent tiles in 2 registers and emitted as
// conflict-free smem atomicAdds (bank = 8*tig - gid, all 32 distinct).
//   j = base + 128k + m  =>  C(n) = sum_st sum_m D_st[m][m+n]
//   pa[k][m] = p[base+128k+m]  (16 x 128 fp32)
//   gb[k][u] = g[base+128k+u]  (16 x 384 fp32)

#define NL        256
#define NLAGS     250
#define KROWS     16
#define SUPER     2048
#define PAW       132
#define GBW       388
#define PA_F      (KROWS * PAW)       // 2112
#define GB_F      (KROWS * GBW)       // 6208
#define BUF_F     (PA_F + GB_F)       // 8320 floats per buffer
#define SMEM_BYTES (2 * BUF_F * 4)    // 66560 (dynamic)
#define CSW       262                 // Cs row stride: 262+2 = 264 = 8 mod 32
#define NTHREADS  1024
#define MAXBLK    160

__device__ float d_Cpart[MAXBLK][NL];
__device__ float d_sums[MAXBLK][4];
__device__ unsigned int d_ticket;

__device__ __forceinline__ void mma_tf32(float& d0, float& d1, float& d2, float& d3,
                                         uint32_t a0, uint32_t a1, uint32_t a2, uint32_t a3,
                                         uint32_t b0, uint32_t b1) {
    asm volatile(
        "mma.sync.aligned.m16n8k8.row.col.f32.tf32.tf32.f32 "
        "{%0,%1,%2,%3}, {%4,%5,%6,%7}, {%8,%9}, {%0,%1,%2,%3};"
        : "+f"(d0), "+f"(d1), "+f"(d2), "+f"(d3)
        : "r"(a0), "r"(a1), "r"(a2), "r"(a3), "r"(b0), "r"(b1));
}
__device__ __forceinline__ void cpa16(uint32_t dst_smem, const float* src) {
    asm volatile("cp.async.cg.shared.global [%0], [%1], 16;"
                 :: "r"(dst_smem), "l"(src) : "memory");
}
__device__ __forceinline__ uint32_t smem_u32(const void* ptr) {
    uint32_t a;
    asm("{ .reg .u64 t; cvta.to.shared.u64 t, %1; cvt.u32.u64 %0, t; }"
        : "=r"(a) : "l"(ptr));
    return a;
}

__device__ __forceinline__ void fill_tiles(float* pab, float* gbb,
                                           const float* p, const float* g,
                                           long long base, int T, int tid) {
    if (base + (long long)(128 * (KROWS - 1) + 384) <= (long long)T) {
        if (tid < 512) {                       // pa: 512 x 16B
            int k = tid >> 5, seg = tid & 31;
            cpa16(smem_u32(pab + k * PAW + 4 * seg), p + base + 128 * k + 4 * seg);
        }
        for (int idx = tid; idx < 1536; idx += NTHREADS) {  // gb: 1536 x 16B
            int k = idx / 96, seg = idx - 96 * k;
            cpa16(smem_u32(gbb + k * GBW + 4 * seg), g + base + 128 * k + 4 * seg);
        }
    } else {
        for (int idx = tid; idx < 2048; idx += NTHREADS) {
            int k = idx >> 7, m = idx & 127;
            long long gi = base + idx;
            pab[k * PAW + m] = (gi < T) ? p[gi] : 0.f;
        }
        for (int idx = tid; idx < KROWS * 384; idx += NTHREADS) {
            int k = idx / 384, u = idx - 384 * k;
            long long gi = base + 128 * k + u;
            gbb[k * GBW + u] = (gi < T) ? g[gi] : 0.f;
        }
    }
    asm volatile("cp.async.commit_group;" ::: "memory");
}

__global__ void __launch_bounds__(NTHREADS, 1)
ccc_tf32_kernel(const float* __restrict__ p, const float* __restrict__ g,
                float* __restrict__ out, int T, int nst) {
    extern __shared__ float sm[];
    __shared__ float Cs[4][CSW];       // lag accumulators (tig rows)
    __shared__ float red[NTHREADS / 32];
    __shared__ int   s_last;

    const int tid  = threadIdx.x;
    const int wid  = tid >> 5, lane = tid & 31;
    const int gid  = lane >> 2, tig = lane & 3;
    const int mi   = wid & 7, q = wid >> 3;
    const int m0   = mi * 16;
    const int toff = (q == 0) ? 0 : (q == 1) ? 9 : (q == 2) ? 18 : 26;
    const int ntq  = (q < 2) ? 9 : 8;

    for (int i = tid; i < 4 * CSW; i += NTHREADS)
        (&Cs[0][0])[i] = 0.f;

    float s_p = 0.f, q_p = 0.f, s_g = 0.f, q_g = 0.f;

    int buf = 0;
    if (blockIdx.x < (unsigned)nst)
        fill_tiles(sm, sm + PA_F, p, g, (long long)blockIdx.x * SUPER, T, tid);

    for (int c = blockIdx.x; c < nst; c += gridDim.x) {
        asm volatile("cp.async.wait_group 0;" ::: "memory");
        __syncthreads();

        const float* pab = sm + buf * BUF_F;
        const float* gbb = pab + PA_F;

        int nc = c + gridDim.x;
        if (nc < nst) {
            float* npa = sm + (buf ^ 1) * BUF_F;
            fill_tiles(npa, npa + PA_F, p, g, (long long)nc * SUPER, T, tid);
        }

        // ---- stats from smem ----
#pragma unroll
        for (int it = 0; it < 2; it++) {
            int i = tid + it * NTHREADS;
            int k = i >> 7, m = i & 127;
            float v = pab[k * PAW + m];
            s_p += v; q_p += v * v;
            float w = gbb[k * GBW + m];
            s_g += w; q_g += w * w;
        }

        // ---- A fragments (2 k8-steps) ----
        uint32_t af[2][4];
#pragma unroll
        for (int ks = 0; ks < 2; ks++) {
            int kr = 8 * ks + tig;
            af[ks][0] = __float_as_uint(pab[kr * PAW + m0 + gid]);
            af[ks][1] = __float_as_uint(pab[kr * PAW + m0 + gid + 8]);
            af[ks][2] = __float_as_uint(pab[(kr + 4) * PAW + m0 + gid]);
            af[ks][3] = __float_as_uint(pab[(kr + 4) * PAW + m0 + gid + 8]);
        }

        // ---- banded tiles, carry-chained diagonal emission ----
        float carry0 = 0.f, carry1 = 0.f;
        const int ndiag = 2 * tig - gid;     // lag offset within tile
        float* Crow = &Cs[tig][0];
#pragma unroll
        for (int t = 0; t < 9; t++) {
            if (t < ntq) {
                const int uc = m0 + 8 * (toff + t) + gid;
                float d0 = 0.f, d1 = 0.f, d2 = 0.f, d3 = 0.f;
#pragma unroll
                for (int ks = 0; ks < 2; ks++) {
                    int kr = 8 * ks + tig;
                    uint32_t b0 = __float_as_uint(gbb[kr * GBW + uc]);
                    uint32_t b1 = __float_as_uint(gbb[(kr + 4) * GBW + uc]);
                    mma_tf32(d0, d1, d2, d3,
                             af[ks][0], af[ks][1], af[ks][2], af[ks][3], b0, b1);
                }
                // lags for (d2,d3): n2 = 8*(toff+t) - 8 + ndiag (+0/+1)
                // == lags of previous tile's (d0,d1) -> fold with carry
                int n2 = 8 * (toff + t) - 8 + ndiag;
                float c0 = d2 + carry0;
                float c1 = d3 + carry1;
                if ((unsigned)n2       < NLAGS) atomicAdd(Crow + n2,     c0);
                if ((unsigned)(n2 + 1) < NLAGS) atomicAdd(Crow + n2 + 1, c1);
                carry0 = d0; carry1 = d1;
            }
        }
        // flush last tile's (d0,d1)
        {
            int nf = 8 * (toff + ntq - 1) + ndiag;
            if ((unsigned)nf       < NLAGS) atomicAdd(Crow + nf,     carry0);
            if ((unsigned)(nf + 1) < NLAGS) atomicAdd(Crow + nf + 1, carry1);
        }
        buf ^= 1;
    }
    __syncthreads();

    // ---- fold 4 tig rows -> d_Cpart ----
    if (tid < NL) {
        float v = 0.f;
        if (tid < NLAGS)
            v = (Cs[0][tid] + Cs[1][tid]) + (Cs[2][tid] + Cs[3][tid]);
        d_Cpart[blockIdx.x][tid] = v;
    }

    // ---- block-reduce scalar sums ----
    float vals[4] = {s_p, q_p, s_g, q_g};
    for (int v = 0; v < 4; v++) {
        float x = vals[v];
#pragma unroll
        for (int off = 16; off > 0; off >>= 1)
            x += __shfl_down_sync(0xFFFFFFFFu, x, off);
        if (lane == 0) red[wid] = x;
        __syncthreads();
        if (tid == 0) {
            float s = 0.f;
            for (int w = 0; w < NTHREADS / 32; w++) s += red[w];
            d_sums[blockIdx.x][v] = s;
        }
        __syncthreads();
    }

    // ---- last-block election ----
    __threadfence();
    if (tid == 0) {
        unsigned int old = atomicAdd(&d_ticket, 1u);
        s_last = (old == gridDim.x - 1) ? 1 : 0;
    }
    __syncthreads();
    if (!s_last) return;

    // ================= finalize (last block) =================
    const int nblk = gridDim.x;
    __shared__ double sh_sums[4];
    __shared__ double prefp[NL];
    __shared__ double prefq[NL];
    __shared__ double cccsh[NL];

    double Cn = 0.0;
    if (tid < NL) {
        const int lag = tid;
        float a0 = 0.f, a1 = 0.f, a2 = 0.f, a3 = 0.f;
        int b = 0;
        for (; b + 3 < nblk; b += 4) {
            a0 += d_Cpart[b    ][lag];
            a1 += d_Cpart[b + 1][lag];
            a2 += d_Cpart[b + 2][lag];
            a3 += d_Cpart[b + 3][lag];
        }
        for (; b < nblk; b++) a0 += d_Cpart[b][lag];
        Cn = (double)((a0 + a1) + (a2 + a3));
    }

    if (tid < 128) {
        int v = tid >> 5, ln = tid & 31;
        double sv = 0.0;
        for (int b = ln; b < nblk; b += 32) sv += (double)d_sums[b][v];
#pragma unroll
        for (int off = 16; off > 0; off >>= 1)
            sv += __shfl_down_sync(0xFFFFFFFFu, sv, off);
        if (ln == 0) sh_sums[v] = sv;
    }

    if (tid < NL) {
        double w = (tid >= 1) ? (double)p[T - tid] : 0.0;
        prefp[tid] = w;
        prefq[tid] = w * w;
    }
    __syncthreads();
#pragma unroll
    for (int off = 1; off < NL; off <<= 1) {
        double a = 0.0, b = 0.0;
        if (tid < NL && tid >= off) { a = prefp[tid - off]; b = prefq[tid - off]; }
        __syncthreads();
        if (tid < NL) { prefp[tid] += a; prefq[tid] += b; }
        __syncthreads();
    }

    double ccc = 0.0;
    if (tid < NLAGS) {
        double tp = prefp[tid], tq = prefq[tid];
        const double Td  = (double)T;
        const double rT  = 1.0 / Td;
        const double rT1 = 1.0 / (Td - 1.0);
        double Sp = sh_sums[0] - tp, Qp = sh_sums[1] - tq;
        double Sg = sh_sums[2],      Qg = sh_sums[3];
        double mean_gt   = Sg * rT;
        double var_gt    = (Qg - Sg * Sg * rT) * rT1;
        double mean_pred = Sp * rT;
        double var_pred  = (Qp - Sp * Sp * rT) * rT1;
        double cov       = (Cn - mean_gt * Sp) * rT;
        double dm        = mean_gt - mean_pred;
        ccc = 2.0 * cov / (var_gt + var_pred + dm * dm);
    }
    if (tid < NL) cccsh[tid] = ccc;
    __syncthreads();
#pragma unroll
    for (int off = NL / 2; off > 0; off >>= 1) {
        if (tid < off) cccsh[tid] += cccsh[tid + off];
        __syncthreads();
    }
    if (tid == 0) {
        out[0] = (float)(1.0 - cccsh[0] / (double)NLAGS);
        d_ticket = 0;
    }
}

extern "C" void kernel_launch(void* const* d_in, const int* in_sizes, int n_in,
                              void* d_out, int out_size) {
    const float* p = (const float*)d_in[0];
    const float* g = (const float*)d_in[1];
    int T = in_sizes[0];
    int nst = (T + SUPER - 1) / SUPER;
    int grid = nst < 148 ? nst : 148;
    cudaFuncSetAttribute(ccc_tf32_kernel,
                         cudaFuncAttributeMaxDynamicSharedMemorySize, SMEM_BYTES);
    ccc_tf32_kernel<<<grid, NTHREADS, SMEM_BYTES>>>(p, g, (float*)d_out, T, nst);
}

// round 17
// speedup vs baseline: 1.3624x; 1.3624x over previous
#include <cuda_runtime.h>
#include <cuda_bf16.h>
#include <cstdint>

// CrossCCC via warp-level bf16 MMA (m16n8k16). Banded N, carry-chained
// diagonal pairs, private per-(warp,tig) smem lag rows with a 6*tig
// rotation (bank = 8*tig - gid : all 32 lanes distinct). No register
// arrays (no spills), no atomics. 245 blocks, 2 CTAs/SM.
//   j = base + 128k + m ; A[m][k]=p[base+128k+m] (128x32 bf16)
//                         B[u][k]=g[base+128k+u] (384x32 bf16)

#define NL        256
#define NLAGS     250
#define KC        32
#define SUPER     4096
#define UW        384
#define GWIN      (128 * (KC - 1) + UW)  // 4448
#define NTHREADS  512
#define MAXBLK    256
#define W         20                      // tile row stride in 32-bit words

#define PA_W      (128 * W)               // 2560 words
#define GB_W      (384 * W)               // 7680 words
#define CS_OFF    (PA_W + GB_W)           // 10240 words
#define SMEM_BYTES ((CS_OFF + 64 * NL) * 4)   // 106496 bytes

__device__ float d_Cpart[MAXBLK][NL];
__device__ float d_sums[MAXBLK][4];
__device__ unsigned int d_ticket;

__device__ __forceinline__ uint32_t pack_bf16x2(float lo, float hi) {
    uint32_t r;
    asm("cvt.rn.bf16x2.f32 %0, %1, %2;" : "=r"(r) : "f"(hi), "f"(lo));
    return r;
}
__device__ __forceinline__ void mma_bf16(float& d0, float& d1, float& d2, float& d3,
                                         uint32_t a0, uint32_t a1, uint32_t a2, uint32_t a3,
                                         uint32_t b0, uint32_t b1) {
    asm volatile(
        "mma.sync.aligned.m16n8k16.row.col.f32.bf16.bf16.f32 "
        "{%0,%1,%2,%3}, {%4,%5,%6,%7}, {%8,%9}, {%0,%1,%2,%3};"
        : "+f"(d0), "+f"(d1), "+f"(d2), "+f"(d3)
        : "r"(a0), "r"(a1), "r"(a2), "r"(a3), "r"(b0), "r"(b1));
}

__global__ void __launch_bounds__(NTHREADS, 2)
ccc_mma_kernel(const float* __restrict__ p, const float* __restrict__ g,
               float* __restrict__ out, int T, int nst) {
    extern __shared__ uint32_t smw[];
    uint32_t* pa32 = smw;                 // [128][W]
    uint32_t* gb32 = smw + PA_W;          // [384][W]
    float*    Cs   = reinterpret_cast<float*>(smw + CS_OFF);  // [64][NL]

    __shared__ float red[NTHREADS / 32];
    __shared__ int   s_last;

    const int tid  = threadIdx.x;
    const int wid  = tid >> 5, lane = tid & 31;
    const int gid  = lane >> 2, tig = lane & 3;
    const int mi   = wid & 7, half = wid >> 3;
    const int m0   = mi * 16;
    const int toff = 17 * half;
    const int ndiag = 2 * tig - gid;
    const int rot   = 6 * tig;

    for (int i = tid; i < 64 * NL; i += NTHREADS) Cs[i] = 0.f;

    float s_p = 0.f, q_p = 0.f, s_g = 0.f, q_g = 0.f;

    for (int st = blockIdx.x; st < nst; st += gridDim.x) {
        const long long base = (long long)st * SUPER;
        const int lim = (int)min((long long)0x7FFFFFFF, (long long)T - base);
        const bool safe = (base + GWIN <= (long long)T);
        __syncthreads();

        // ---- pa fill: word cells (m, k2); verified R12 layout ----
#pragma unroll
        for (int it = 0; it < 4; it++) {
            int c = it * NTHREADS + tid;
            int m = (c >> 2) & 127;
            int k2 = (c & 3) | (it << 2);
            int j0 = 256 * k2 + m;
            float v0, v1;
            if (safe) { v0 = p[base + j0]; v1 = p[base + j0 + 128]; }
            else {
                v0 = (j0       < lim) ? p[base + j0]       : 0.f;
                v1 = (j0 + 128 < lim) ? p[base + j0 + 128] : 0.f;
            }
            s_p += v0 + v1; q_p += v0 * v0 + v1 * v1;
            pa32[m * W + k2] = pack_bf16x2(v0, v1);
        }
        // ---- gb fill ----
#pragma unroll
        for (int it = 0; it < 12; it++) {
            const int chunk = it % 3, k2hi = it / 3;
            int c = it * NTHREADS + tid;
            int u = chunk * 128 + ((c >> 2) & 127);
            int k2 = (c & 3) | (k2hi << 2);
            int j0 = 256 * k2 + u;
            float v0, v1;
            if (safe) { v0 = g[base + j0]; v1 = g[base + j0 + 128]; }
            else {
                v0 = (j0       < lim) ? g[base + j0]       : 0.f;
                v1 = (j0 + 128 < lim) ? g[base + j0 + 128] : 0.f;
            }
            if (chunk == 0) { s_g += v0 + v1; q_g += v0 * v0 + v1 * v1; }
            gb32[u * W + k2] = pack_bf16x2(v0, v1);
        }
        __syncthreads();

        // ---- A fragments (2 k-steps), verified layout ----
        uint32_t af00, af01, af02, af03, af10, af11, af12, af13;
        {
            int r0 = (m0 + gid) * W + tig;
            af00 = pa32[r0];          af01 = pa32[r0 + 8 * W];
            af02 = pa32[r0 + 4];      af03 = pa32[r0 + 8 * W + 4];
            af10 = pa32[r0 + 8];      af11 = pa32[r0 + 8 * W + 8];
            af12 = pa32[r0 + 12];     af13 = pa32[r0 + 8 * W + 12];
        }

        // ---- banded mainloop with carry-chained pair emission ----
        float carry0 = 0.f, carry1 = 0.f;
        float* Crow = Cs + (wid * 4 + tig) * NL;
#pragma unroll
        for (int t = 0; t < 17; t++) {
            const int s = toff + t;
            const int brow = (m0 + 8 * s + gid) * W + tig;
            float d0 = 0.f, d1 = 0.f, d2 = 0.f, d3 = 0.f;
            {
                uint32_t b0 = gb32[brow];
                uint32_t b1 = gb32[brow + 4];
                mma_bf16(d0, d1, d2, d3, af00, af01, af02, af03, b0, b1);
            }
            {
                uint32_t b0 = gb32[brow + 8];
                uint32_t b1 = gb32[brow + 12];
                mma_bf16(d0, d1, d2, d3, af10, af11, af12, af13, b0, b1);
            }
            // (d2,d3) lags == previous tile's (d0,d1) lags -> fold with carry
            int n2 = 8 * s - 8 + ndiag;
            float c0 = d2 + carry0;
            float c1 = d3 + carry1;
            if ((unsigned)n2       < NLAGS) Crow[(n2     + rot) & 255] += c0;
            if ((unsigned)(n2 + 1) < NLAGS) Crow[(n2 + 1 + rot) & 255] += c1;
            carry0 = d0; carry1 = d1;
        }
        // flush last tile's (d0,d1)
        {
            int nf = 8 * (toff + 16) + ndiag;
            if ((unsigned)nf       < NLAGS) Crow[(nf     + rot) & 255] += carry0;
            if ((unsigned)(nf + 1) < NLAGS) Crow[(nf + 1 + rot) & 255] += carry1;
        }
    }
    __syncthreads();

    // ---- fold 64 rotated rows -> d_Cpart ----
    if (tid < NL) {
        const int n = tid;
        float v = 0.f;
#pragma unroll 4
        for (int r = 0; r < 64; r++)
            v += Cs[r * NL + ((n + 6 * (r & 3)) & 255)];
        d_Cpart[blockIdx.x][n] = v;
    }

    // ---- block-reduce scalar sums ----
    float vals[4] = {s_p, q_p, s_g, q_g};
    for (int v = 0; v < 4; v++) {
        float x = vals[v];
#pragma unroll
        for (int off = 16; off > 0; off >>= 1)
            x += __shfl_down_sync(0xFFFFFFFFu, x, off);
        if (lane == 0) red[wid] = x;
        __syncthreads();
        if (tid == 0) {
            float s = 0.f;
            for (int w = 0; w < NTHREADS / 32; w++) s += red[w];
            d_sums[blockIdx.x][v] = s;
        }
        __syncthreads();
    }

    // ---- last-block election ----
    __threadfence();
    if (tid == 0) {
        unsigned int old = atomicAdd(&d_ticket, 1u);
        s_last = (old == gridDim.x - 1) ? 1 : 0;
    }
    __syncthreads();
    if (!s_last) return;

    // ================= finalize (last block; scratch aliases tiles) ====
    const int nblk = gridDim.x;
    double* prefp = reinterpret_cast<double*>(smw);          // 256 doubles
    double* prefq = prefp + NL;
    double* cccsh = prefq + NL;
    __shared__ double sh_sums[4];

    double Cn = 0.0;
    if (tid < NL) {
        const int lag = tid;
        float a0 = 0.f, a1 = 0.f, a2 = 0.f, a3 = 0.f;
        int b = 0;
        for (; b + 3 < nblk; b += 4) {
            a0 += d_Cpart[b    ][lag];
            a1 += d_Cpart[b + 1][lag];
            a2 += d_Cpart[b + 2][lag];
            a3 += d_Cpart[b + 3][lag];
        }
        for (; b < nblk; b++) a0 += d_Cpart[b][lag];
        Cn = (double)((a0 + a1) + (a2 + a3));
    }

    if (tid < 128) {
        int v = tid >> 5, ln = tid & 31;
        double sv = 0.0;
        for (int b = ln; b < nblk; b += 32) sv += (double)d_sums[b][v];
#pragma unroll
        for (int off = 16; off > 0; off >>= 1)
            sv += __shfl_down_sync(0xFFFFFFFFu, sv, off);
        if (ln == 0) sh_sums[v] = sv;
    }
    __syncthreads();   // smw reads (Cs fold) done before aliasing writes below? fold was before ticket; safe

    if (tid < NL) {
        double w = (tid >= 1) ? (double)p[T - tid] : 0.0;
        prefp[tid] = w;
        prefq[tid] = w * w;
    }
    __syncthreads();
#pragma unroll
    for (int off = 1; off < NL; off <<= 1) {
        double a = 0.0, b = 0.0;
        if (tid < NL && tid >= off) { a = prefp[tid - off]; b = prefq[tid - off]; }
        __syncthreads();
        if (tid < NL) { prefp[tid] += a; prefq[tid] += b; }
        __syncthreads();
    }

    double ccc = 0.0;
    if (tid < NLAGS) {
        double tp = prefp[tid], tq = prefq[tid];
        const double Td  = (double)T;
        const double rT  = 1.0 / Td;
        const double rT1 = 1.0 / (Td - 1.0);
        double Sp = sh_sums[0] - tp, Qp = sh_sums[1] - tq;
        double Sg = sh_sums[2],      Qg = sh_sums[3];
        double mean_gt   = Sg * rT;
        double var_gt    = (Qg - Sg * Sg * rT) * rT1;
        double mean_pred = Sp * rT;
        double var_pred  = (Qp - Sp * Sp * rT) * rT1;
        double cov       = (Cn - mean_gt * Sp) * rT;
        double dm        = mean_gt - mean_pred;
        ccc = 2.0 * cov / (var_gt + var_pred + dm * dm);
    }
    if (tid < NL) cccsh[tid] = ccc;
    __syncthreads();
#pragma unroll
    for (int off = NL / 2; off > 0; off >>= 1) {
        if (tid < off) cccsh[tid] += cccsh[tid + off];
        __syncthreads();
    }
    if (tid == 0) {
        out[0] = (float)(1.0 - cccsh[0] / (double)NLAGS);
        d_ticket = 0;
    }
}

extern "C" void kernel_launch(void* const* d_in, const int* in_sizes, int n_in,
                              void* d_out, int out_size) {
    const float* p = (const float*)d_in[0];
    const float* g = (const float*)d_in[1];
    int T = in_sizes[0];
    int nst = (T + SUPER - 1) / SUPER;
    int grid = nst < MAXBLK ? nst : MAXBLK;
    cudaFuncSetAttribute(ccc_mma_kernel,
                         cudaFuncAttributeMaxDynamicSharedMemorySize, SMEM_BYTES);
    ccc_mma_kernel<<<grid, NTHREADS, SMEM_BYTES>>>(p, g, (float*)d_out, T, nst);
}